// round 16
// baseline (speedup 1.0000x reference)
#include <cuda_runtime.h>
#include <cuda_fp16.h>
#include <cstdint>

#define NH 32
#define NHK 8
#define GQ 4
#define HD 128
#define NBATCH 4
#define MAXT 4096
#define NSLOTS 8192
#define SCALE_LOG2E 0.1275174355f   // (1/sqrt(128)) * log2(e)
#define FIXMAX 8.0f
#define ONESH2 0x3C003C00u          // half2(1.0, 1.0)

#define BM 128
#define BN 64
#define NTHREADS 256
#define NPERSIST 152

#define SSTR 136                    // half stride per row (272B, conflict-free)
#define SQ_HALF (BM * SSTR)         // 17408
#define SKV_HALF (BN * SSTR)        // 8704
#define STAGE_F32 (BM * HD)         // 16384 floats
#define SMEM_HALVES (SQ_HALF + 4 * SKV_HALF + 2 * STAGE_F32)
#define SMEM_BYTES (SMEM_HALVES * 2)   // 169984 B

// fp16 scratch (pre-converted K/V only)
__device__ __half g_kh[(size_t)MAXT * NHK * HD];
__device__ __half g_vh[(size_t)MAXT * NHK * HD];
__device__ int g_ctr;
__device__ unsigned char g_slotflag[NSLOTS];   // slot written by scatter

__device__ __forceinline__ uint32_t ph2(float a, float b) {
    half2 h = __floats2half2_rn(a, b);
    return *reinterpret_cast<uint32_t*>(&h);
}
__device__ __forceinline__ uint32_t sptr(const void* p) {
    return (uint32_t)__cvta_generic_to_shared(p);
}
__device__ __forceinline__ float fexp2(float x) {
    float r;
    asm("ex2.approx.f32 %0, %1;" : "=f"(r) : "f"(x));
    return r;
}
__device__ __forceinline__ void cpa16(uint32_t dst, const void* src) {
    asm volatile("cp.async.cg.shared.global [%0], [%1], 16;" :: "r"(dst), "l"(src));
}
__device__ __forceinline__ void cpa_commit() { asm volatile("cp.async.commit_group;"); }
__device__ __forceinline__ void cpa_wait0()  { asm volatile("cp.async.wait_group 0;"); }

__device__ __forceinline__ void ldsm_x4(uint32_t* r, uint32_t addr) {
    asm volatile("ldmatrix.sync.aligned.m8n8.x4.shared.b16 {%0,%1,%2,%3}, [%4];"
                 : "=r"(r[0]), "=r"(r[1]), "=r"(r[2]), "=r"(r[3]) : "r"(addr));
}
__device__ __forceinline__ void ldsm_x4_t(uint32_t* r, uint32_t addr) {
    asm volatile("ldmatrix.sync.aligned.m8n8.x4.trans.shared.b16 {%0,%1,%2,%3}, [%4];"
                 : "=r"(r[0]), "=r"(r[1]), "=r"(r[2]), "=r"(r[3]) : "r"(addr));
}
__device__ __forceinline__ void mma16816(float c[4],
                                         const uint32_t a[4],
                                         uint32_t b0, uint32_t b1) {
    asm volatile("mma.sync.aligned.m16n8k16.row.col.f32.f16.f16.f32 "
                 "{%0,%1,%2,%3}, {%4,%5,%6,%7}, {%8,%9}, {%0,%1,%2,%3};"
                 : "+f"(c[0]), "+f"(c[1]), "+f"(c[2]), "+f"(c[3])
                 : "r"(a[0]), "r"(a[1]), "r"(a[2]), "r"(a[3]), "r"(b0), "r"(b1));
}

extern __shared__ __align__(16) half smem_h[];

__device__ __forceinline__ void issue_kv(half* kb, half* vb,
                                         int t, int seq_start, int seq_end,
                                         int hk, int k0) {
#pragma unroll
    for (int u = t; u < BN * 16; u += NTHREADS) {
        int row = u >> 4, seg = u & 15;
        int tok = seq_start + k0 + row;
        if (tok > seq_end - 1) tok = seq_end - 1;
        size_t base = (size_t)tok * NHK * HD + (size_t)hk * HD + seg * 8;
        cpa16(sptr(kb + row * SSTR + seg * 8), g_kh + base);
        cpa16(sptr(vb + row * SSTR + seg * 8), g_vh + base);
    }
}

__device__ __forceinline__ void issue_qstage(float* stage, const float* q,
                                             int t, int seq_start, int seq_end,
                                             int h, int q0) {
#pragma unroll
    for (int u = t; u < BM * (HD / 4); u += NTHREADS) {
        int row = u >> 5, c4 = u & 31;
        int tok = seq_start + q0 + row;
        if (tok > seq_end - 1) tok = seq_end - 1;
        cpa16(sptr(stage + row * HD + c4 * 4),
              q + (size_t)tok * NH * HD + (size_t)h * HD + c4 * 4);
    }
}

__device__ __forceinline__ void map_item(int item, const int* nb_, int maxnb,
                                         int& q0, int& b, int& h) {
    int L = maxnb - 1;
    b = 0; h = 0;
    int i = item;
    for (; L >= 0; L--) {
        int ids[NBATCH], n = 0;
#pragma unroll
        for (int bb = 0; bb < NBATCH; bb++)
            if (nb_[bb] > L) ids[n++] = bb;
        int m = n * NH;
        if (i < m) { b = ids[i / NH]; h = i % NH; break; }
        i -= m;
    }
    q0 = L * BM;
}

__global__ void __launch_bounds__(NTHREADS, 1)
attn_kernel(const float* __restrict__ q, const int* __restrict__ cu,
            float* __restrict__ out)
{
    __shared__ int s_item;

    half*  sQ    = smem_h;
    half*  sK    = sQ + SQ_HALF;       // 2 buffers
    half*  sV    = sK + 2 * SKV_HALF;  // 2 buffers
    float* stage = reinterpret_cast<float*>(sV + 2 * SKV_HALF);

    const int t    = threadIdx.x;
    const int w    = t >> 5;
    const int lane = t & 31;
    const int g    = lane >> 2;
    const int tg   = lane & 3;

    int nb_[NBATCH], maxnb = 0, total = 0;
#pragma unroll
    for (int bb = 0; bb < NBATCH; bb++) {
        int l = cu[bb + 1] - cu[bb];
        nb_[bb] = (l + BM - 1) / BM;
        if (nb_[bb] > maxnb) maxnb = nb_[bb];
        total += nb_[bb];
    }
    total *= NH;

    const int krow = (lane & 7) + ((lane >> 4) << 3);
    const int kcol = ((lane >> 3) & 1) * 8;
    const int vrow = lane & 15;
    const int vcol = (lane >> 4) << 3;

    // first ticket + Q stage
    if (t == 0) s_item = atomicAdd(&g_ctr, 1);
    __syncthreads();
    int item = s_item;
    if (item < total) {
        int q0, b, h;
        map_item(item, nb_, maxnb, q0, b, h);
        issue_qstage(stage, q, t, cu[b], cu[b + 1], h, q0);
        cpa_commit();
    }

    while (item < total) {
        int q0, b, h;
        map_item(item, nb_, maxnb, q0, b, h);
        const int seq_start = cu[b];
        const int seq_end   = cu[b + 1];
        const int len       = seq_end - seq_start;
        const int hk        = h / GQ;

        // stage (f32 Q) ready; convert to scaled fp16 sQ
        cpa_wait0();
        __syncthreads();
#pragma unroll
        for (int u = t; u < BM * 16; u += NTHREADS) {
            int row = u >> 4, seg = u & 15;
            const float* src = stage + row * HD + seg * 8;
            float4 f0 = *reinterpret_cast<const float4*>(src);
            float4 f1 = *reinterpret_cast<const float4*>(src + 4);
            uint4 o;
            o.x = ph2(f0.x * SCALE_LOG2E, f0.y * SCALE_LOG2E);
            o.y = ph2(f0.z * SCALE_LOG2E, f0.w * SCALE_LOG2E);
            o.z = ph2(f1.x * SCALE_LOG2E, f1.y * SCALE_LOG2E);
            o.w = ph2(f1.z * SCALE_LOG2E, f1.w * SCALE_LOG2E);
            *reinterpret_cast<uint4*>(sQ + row * SSTR + seg * 8) = o;
        }
        issue_kv(sK, sV, t, seq_start, seq_end, hk, 0);
        cpa_commit();
        __syncthreads();   // sQ visible

        const int nk     = (len < q0 + BM) ? len : (q0 + BM);
        const int ntiles = (nk + BN - 1) / BN;

        // ---- preload Q fragments ----
        uint32_t qf[8][4];
        {
            int qrow = w * 16 + (lane & 15);
            int qcol = (lane >> 4) << 3;
            const half* qb = sQ + qrow * SSTR + qcol;
#pragma unroll
            for (int kb = 0; kb < 8; kb++)
                ldsm_x4(qf[kb], sptr(qb + kb * 16));
        }

        // next ticket; wait KV tile0; then prefetch next item's Q stage
        if (t == 0) s_item = atomicAdd(&g_ctr, 1);
        cpa_wait0();
        __syncthreads();
        int next = s_item;
        if (next < total) {
            int nq0, nb2, nh2;
            map_item(next, nb_, maxnb, nq0, nb2, nh2);
            issue_qstage(stage, q, t, cu[nb2], cu[nb2 + 1], nh2, nq0);
            cpa_commit();
        }

        float O[16][4];
#pragma unroll
        for (int nb = 0; nb < 16; nb++)
#pragma unroll
            for (int i = 0; i < 4; i++) O[nb][i] = 0.0f;
        float lc[4] = {0.0f, 0.0f, 0.0f, 0.0f};

        const int row0 = q0 + w * 16 + g;
        const int row1 = row0 + 8;
        const int wband_lo = q0 + w * 16;
        const int wband_hi = q0 + w * 16 + 15;

        for (int it = 0; it < ntiles; it++) {
            const int k0  = it * BN;
            const int cur = it & 1;

            if (it + 1 < ntiles) {
                issue_kv(sK + (cur ^ 1) * SKV_HALF, sV + (cur ^ 1) * SKV_HALF,
                         t, seq_start, seq_end, hk, k0 + BN);
                cpa_commit();
            }

            if (k0 <= wband_hi) {
                const half* kb = sK + cur * SKV_HALF;
                const half* vb = sV + cur * SKV_HALF;
                const bool do_mask = (k0 + BN - 1 > wband_lo);

                float S[8][4];
#pragma unroll
                for (int nb = 0; nb < 8; nb++)
#pragma unroll
                    for (int i = 0; i < 4; i++) S[nb][i] = 0.0f;

                // ---- QK chunk0 (cols 0..31) ----
#pragma unroll
                for (int ks = 0; ks < 8; ks++) {
#pragma unroll
                    for (int p = 0; p < 2; p++) {
                        uint32_t fk[4];
                        ldsm_x4(fk, sptr(kb + (p * 16 + krow) * SSTR + ks * 16 + kcol));
                        mma16816(S[2 * p],     qf[ks], fk[0], fk[1]);
                        mma16816(S[2 * p + 1], qf[ks], fk[2], fk[3]);
                    }
                }

                // ---- softmax chunk0 -> pa[0..1] ----
                uint32_t pa[4][4];
                if (do_mask) {
#pragma unroll
                    for (int nb = 0; nb < 4; nb++) {
                        int j0 = k0 + nb * 8 + 2 * tg;
                        int j1 = j0 + 1;
                        if (j0 > row0) S[nb][0] = -1e30f;
                        if (j1 > row0) S[nb][1] = -1e30f;
                        if (j0 > row1) S[nb][2] = -1e30f;
                        if (j1 > row1) S[nb][3] = -1e30f;
                    }
                }
#pragma unroll
                for (int nb = 0; nb < 4; nb++) {
                    float p0 = fexp2(S[nb][0] - FIXMAX);
                    float p1 = fexp2(S[nb][1] - FIXMAX);
                    float p2 = fexp2(S[nb][2] - FIXMAX);
                    float p3 = fexp2(S[nb][3] - FIXMAX);
                    int kb2 = nb >> 1;
                    int off = (nb & 1) * 2;
                    pa[kb2][off]     = ph2(p0, p1);
                    pa[kb2][off + 1] = ph2(p2, p3);
                }

                // ---- QK chunk1 (cols 32..63), overlaps softmax0 retire ----
#pragma unroll
                for (int ks = 0; ks < 8; ks++) {
#pragma unroll
                    for (int p = 2; p < 4; p++) {
                        uint32_t fk[4];
                        ldsm_x4(fk, sptr(kb + (p * 16 + krow) * SSTR + ks * 16 + kcol));
                        mma16816(S[2 * p],     qf[ks], fk[0], fk[1]);
                        mma16816(S[2 * p + 1], qf[ks], fk[2], fk[3]);
                    }
                }

                // ---- l + PV chunk0 ----
                mma16816(lc, pa[0], ONESH2, ONESH2);
                mma16816(lc, pa[1], ONESH2, ONESH2);
#pragma unroll
                for (int kb2 = 0; kb2 < 2; kb2++) {
#pragma unroll
                    for (int p = 0; p < 8; p++) {
                        uint32_t fv[4];
                        ldsm_x4_t(fv, sptr(vb + (kb2 * 16 + vrow) * SSTR + p * 16 + vcol));
                        mma16816(O[2 * p],     pa[kb2], fv[0], fv[1]);
                        mma16816(O[2 * p + 1], pa[kb2], fv[2], fv[3]);
                    }
                }

                // ---- softmax chunk1 -> pa[2..3] ----
                if (do_mask) {
#pragma unroll
                    for (int nb = 4; nb < 8; nb++) {
                        int j0 = k0 + nb * 8 + 2 * tg;
                        int j1 = j0 + 1;
                        if (j0 > row0) S[nb][0] = -1e30f;
                        if (j1 > row0) S[nb][1] = -1e30f;
                        if (j0 > row1) S[nb][2] = -1e30f;
                        if (j1 > row1) S[nb][3] = -1e30f;
                    }
                }
#pragma unroll
                for (int nb = 4; nb < 8; nb++) {
                    float p0 = fexp2(S[nb][0] - FIXMAX);
                    float p1 = fexp2(S[nb][1] - FIXMAX);
                    float p2 = fexp2(S[nb][2] - FIXMAX);
                    float p3 = fexp2(S[nb][3] - FIXMAX);
                    int kb2 = nb >> 1;
                    int off = (nb & 1) * 2;
                    pa[kb2][off]     = ph2(p0, p1);
                    pa[kb2][off + 1] = ph2(p2, p3);
                }

                // ---- l + PV chunk1 ----
                mma16816(lc, pa[2], ONESH2, ONESH2);
                mma16816(lc, pa[3], ONESH2, ONESH2);
#pragma unroll
                for (int kb2 = 2; kb2 < 4; kb2++) {
#pragma unroll
                    for (int p = 0; p < 8; p++) {
                        uint32_t fv[4];
                        ldsm_x4_t(fv, sptr(vb + (kb2 * 16 + vrow) * SSTR + p * 16 + vcol));
                        mma16816(O[2 * p],     pa[kb2], fv[0], fv[1]);
                        mma16816(O[2 * p + 1], pa[kb2], fv[2], fv[3]);
                    }
                }
            }

            if (it + 1 < ntiles) {
                cpa_wait0();
                __syncthreads();
            }
        }

        // ---- epilogue ----
        float inv0 = 1.0f / lc[0];
        float inv1 = 1.0f / lc[2];
        if (row0 < len) {
            float* outr = out + (size_t)(seq_start + row0) * NH * HD + (size_t)h * HD;
#pragma unroll
            for (int nb = 0; nb < 16; nb++)
                *reinterpret_cast<float2*>(outr + nb * 8 + 2 * tg) =
                    make_float2(O[nb][0] * inv0, O[nb][1] * inv0);
        }
        if (row1 < len) {
            float* outr = out + (size_t)(seq_start + row1) * NH * HD + (size_t)h * HD;
#pragma unroll
            for (int nb = 0; nb < 16; nb++)
                *reinterpret_cast<float2*>(outr + nb * 8 + 2 * tg) =
                    make_float2(O[nb][2] * inv1, O[nb][3] * inv1);
        }
        __syncthreads();   // smem reused by next item
        item = next;
    }
}

// ---- preconvert K/V to fp16 + fused f32 scatter + slot flags ----
__device__ __forceinline__ void preconv_one(const float* __restrict__ k,
                                            const float* __restrict__ v,
                                            const int* __restrict__ slot_mapping,
                                            float* __restrict__ kc_out,
                                            float* __restrict__ vc_out,
                                            size_t j)
{
    size_t off = j * 8;
    float4 a = *reinterpret_cast<const float4*>(k + off);
    float4 b = *reinterpret_cast<const float4*>(k + off + 4);
    float4 c = *reinterpret_cast<const float4*>(v + off);
    float4 d = *reinterpret_cast<const float4*>(v + off + 4);

    uint4 ko, vo;
    ko.x = ph2(a.x, a.y); ko.y = ph2(a.z, a.w);
    ko.z = ph2(b.x, b.y); ko.w = ph2(b.z, b.w);
    vo.x = ph2(c.x, c.y); vo.y = ph2(c.z, c.w);
    vo.z = ph2(d.x, d.y); vo.w = ph2(d.z, d.w);
    *reinterpret_cast<uint4*>(g_kh + off) = ko;
    *reinterpret_cast<uint4*>(g_vh + off) = vo;

    // fused scatter: token = j / 128 (NHK*HD/8 chunks per token)
    int tok = (int)(j >> 7);
    int pos = ((int)j & 127) * 8;
    int slot = slot_mapping[tok];
    if (slot >= 0) {
        float* kd = kc_out + (size_t)slot * (NHK * HD) + pos;
        float* vd = vc_out + (size_t)slot * (NHK * HD) + pos;
        *reinterpret_cast<float4*>(kd)     = a;
        *reinterpret_cast<float4*>(kd + 4) = b;
        *reinterpret_cast<float4*>(vd)     = c;
        *reinterpret_cast<float4*>(vd + 4) = d;
        if (((int)j & 127) == 0) g_slotflag[slot] = 1;
    }
}

__global__ void preconv_kv_kernel(const float* __restrict__ k,
                                  const float* __restrict__ v,
                                  const int* __restrict__ slot_mapping,
                                  float* __restrict__ kc_out,
                                  float* __restrict__ vc_out,
                                  int half_n8)
{
    int i = blockIdx.x * blockDim.x + threadIdx.x;
    if (i == 0) g_ctr = 0;
    if (i >= half_n8) return;
    preconv_one(k, v, slot_mapping, kc_out, vc_out, (size_t)i);
    preconv_one(k, v, slot_mapping, kc_out, vc_out, (size_t)(i + half_n8));
}

// copy only slots NOT written by the scatter (disjoint -> no ordering needed)
__global__ void cache_copy_kernel(const float* __restrict__ kc_in,
                                  const float* __restrict__ vc_in,
                                  float* __restrict__ kc_out,
                                  float* __restrict__ vc_out,
                                  int n4)
{
    int i = blockIdx.x * blockDim.x + threadIdx.x;
    if (i >= n4) return;
    int slot = i >> 8;   // 256 float4 per slot (NHK*HD/4)
    if (g_slotflag[slot]) return;
    reinterpret_cast<float4*>(kc_out)[i] = reinterpret_cast<const float4*>(kc_in)[i];
    reinterpret_cast<float4*>(vc_out)[i] = reinterpret_cast<const float4*>(vc_in)[i];
}

extern "C" void kernel_launch(void* const* d_in, const int* in_sizes, int n_in,
                              void* d_out, int out_size)
{
    const float* q  = (const float*)d_in[0];
    const float* k  = (const float*)d_in[1];
    const float* v  = (const float*)d_in[2];
    const float* kc = (const float*)d_in[3];
    const float* vc = (const float*)d_in[4];
    const int* cu   = (const int*)d_in[5];
    const int* slot = (const int*)d_in[6];

    const int T = in_sizes[0] / (NH * HD);

    float* out_attn = (float*)d_out;
    float* out_kc   = out_attn + (size_t)T * NH * HD;
    float* out_vc   = out_kc + (size_t)NSLOTS * NHK * HD;

    static cudaStream_t side = nullptr;
    static cudaEvent_t evf = nullptr, evj = nullptr;
    if (!side) {
        cudaStreamCreateWithFlags(&side, cudaStreamNonBlocking);
        cudaEventCreateWithFlags(&evf, cudaEventDisableTiming);
        cudaEventCreateWithFlags(&evj, cudaEventDisableTiming);
        cudaFuncSetAttribute(attn_kernel,
                             cudaFuncAttributeMaxDynamicSharedMemorySize,
                             SMEM_BYTES);
    }

    // main stream: preconv + fused scatter + flags (alone, full DRAM BW)
    {
        int half_n8 = T * NHK * HD / 16;
        preconv_kv_kernel<<<(half_n8 + 255) / 256, 256>>>(k, v, slot,
                                                          out_kc, out_vc, half_n8);
    }

    // fork AFTER preconv (flags written): flagged-skip copy overlaps attention
    cudaEventRecord(evf, 0);
    cudaStreamWaitEvent(side, evf, 0);
    {
        int n4 = NSLOTS * NHK * HD / 4;
        cache_copy_kernel<<<(n4 + 255) / 256, 256, 0, side>>>(kc, vc, out_kc, out_vc, n4);
    }
    cudaEventRecord(evj, side);

    // main stream: persistent attention (concurrent with side-stream copy)
    attn_kernel<<<NPERSIST, NTHREADS, SMEM_BYTES>>>(q, cu, out_attn);

    cudaStreamWaitEvent(0, evj, 0);
}

// round 17
// speedup vs baseline: 1.0322x; 1.0322x over previous
#include <cuda_runtime.h>
#include <cuda_fp16.h>
#include <cstdint>

#define NH 32
#define NHK 8
#define GQ 4
#define HD 128
#define NBATCH 4
#define MAXT 4096
#define NSLOTS 8192
#define SCALE_LOG2E 0.1275174355f   // (1/sqrt(128)) * log2(e)
#define FIXMAX 8.0f
#define ONESH2 0x3C003C00u          // half2(1.0, 1.0)

#define BM 64                       // q rows per CTA (4 warps x 16 rows)
#define BN 64
#define NTHREADS 128
#define NPERSIST 456                // 152 SMs x 3 CTAs

#define SSTR 136                    // half stride per row (272B, conflict-free)
#define SKV_HALF (BN * SSTR)        // 8704 halves per buffer
#define SMEM_HALVES (4 * SKV_HALF)  // 2xK + 2xV
#define SMEM_BYTES (SMEM_HALVES * 2)   // 69632 B -> 3 CTAs/SM

// fp16 scratch (pre-converted K/V only)
__device__ __half g_kh[(size_t)MAXT * NHK * HD];
__device__ __half g_vh[(size_t)MAXT * NHK * HD];
__device__ int g_ctr;

__device__ __forceinline__ uint32_t ph2(float a, float b) {
    half2 h = __floats2half2_rn(a, b);
    return *reinterpret_cast<uint32_t*>(&h);
}
__device__ __forceinline__ uint32_t sptr(const void* p) {
    return (uint32_t)__cvta_generic_to_shared(p);
}
__device__ __forceinline__ float fexp2(float x) {
    float r;
    asm("ex2.approx.f32 %0, %1;" : "=f"(r) : "f"(x));
    return r;
}
__device__ __forceinline__ void cpa16(uint32_t dst, const void* src) {
    asm volatile("cp.async.cg.shared.global [%0], [%1], 16;" :: "r"(dst), "l"(src));
}
__device__ __forceinline__ void cpa_commit() { asm volatile("cp.async.commit_group;"); }
__device__ __forceinline__ void cpa_wait0()  { asm volatile("cp.async.wait_group 0;"); }

__device__ __forceinline__ void ldsm_x4(uint32_t* r, uint32_t addr) {
    asm volatile("ldmatrix.sync.aligned.m8n8.x4.shared.b16 {%0,%1,%2,%3}, [%4];"
                 : "=r"(r[0]), "=r"(r[1]), "=r"(r[2]), "=r"(r[3]) : "r"(addr));
}
__device__ __forceinline__ void ldsm_x4_t(uint32_t* r, uint32_t addr) {
    asm volatile("ldmatrix.sync.aligned.m8n8.x4.trans.shared.b16 {%0,%1,%2,%3}, [%4];"
                 : "=r"(r[0]), "=r"(r[1]), "=r"(r[2]), "=r"(r[3]) : "r"(addr));
}
__device__ __forceinline__ void mma16816(float c[4],
                                         const uint32_t a[4],
                                         uint32_t b0, uint32_t b1) {
    asm volatile("mma.sync.aligned.m16n8k16.row.col.f32.f16.f16.f32 "
                 "{%0,%1,%2,%3}, {%4,%5,%6,%7}, {%8,%9}, {%0,%1,%2,%3};"
                 : "+f"(c[0]), "+f"(c[1]), "+f"(c[2]), "+f"(c[3])
                 : "r"(a[0]), "r"(a[1]), "r"(a[2]), "r"(a[3]), "r"(b0), "r"(b1));
}

extern __shared__ __align__(16) half smem_h[];

__device__ __forceinline__ void issue_kv(half* kb, half* vb,
                                         int t, int seq_start, int seq_end,
                                         int hk, int k0) {
#pragma unroll
    for (int u = t; u < BN * 16; u += NTHREADS) {
        int row = u >> 4, seg = u & 15;
        int tok = seq_start + k0 + row;
        if (tok > seq_end - 1) tok = seq_end - 1;
        size_t base = (size_t)tok * NHK * HD + (size_t)hk * HD + seg * 8;
        cpa16(sptr(kb + row * SSTR + seg * 8), g_kh + base);
        cpa16(sptr(vb + row * SSTR + seg * 8), g_vh + base);
    }
}

__device__ __forceinline__ void map_item(int item, const int* nb_, int maxnb,
                                         int& q0, int& b, int& h) {
    int L = maxnb - 1;
    b = 0; h = 0;
    int i = item;
    for (; L >= 0; L--) {
        int ids[NBATCH], n = 0;
#pragma unroll
        for (int bb = 0; bb < NBATCH; bb++)
            if (nb_[bb] > L) ids[n++] = bb;
        int m = n * NH;
        if (i < m) { b = ids[i / NH]; h = i % NH; break; }
        i -= m;
    }
    q0 = L * BM;
}

__global__ void __launch_bounds__(NTHREADS, 3)
attn_kernel(const float* __restrict__ q, const int* __restrict__ cu,
            float* __restrict__ out)
{
    __shared__ int s_item;

    half* sK = smem_h;                 // 2 buffers
    half* sV = sK + 2 * SKV_HALF;      // 2 buffers

    const int t    = threadIdx.x;
    const int w    = t >> 5;           // 0..3
    const int lane = t & 31;
    const int g    = lane >> 2;
    const int tg   = lane & 3;

    int nb_[NBATCH], maxnb = 0, total = 0;
#pragma unroll
    for (int bb = 0; bb < NBATCH; bb++) {
        int l = cu[bb + 1] - cu[bb];
        nb_[bb] = (l + BM - 1) / BM;
        if (nb_[bb] > maxnb) maxnb = nb_[bb];
        total += nb_[bb];
    }
    total *= NH;

    const int krow = (lane & 7) + ((lane >> 4) << 3);
    const int kcol = ((lane >> 3) & 1) * 8;
    const int vrow = lane & 15;
    const int vcol = (lane >> 4) << 3;

    // first ticket
    if (t == 0) s_item = atomicAdd(&g_ctr, 1);
    __syncthreads();
    int item = s_item;

    while (item < total) {
        int q0, b, h;
        map_item(item, nb_, maxnb, q0, b, h);
        const int seq_start = cu[b];
        const int seq_end   = cu[b + 1];
        const int len       = seq_end - seq_start;
        const int hk        = h / GQ;

        // issue KV tile0 first (cp.async flight overlaps Q LDGs below)
        issue_kv(sK, sV, t, seq_start, seq_end, hk, 0);
        cpa_commit();

        // ---- Q fragments straight from gmem (ldmatrix-equivalent layout) ----
        uint32_t qf[8][4];
        {
            int rA = q0 + w * 16 + g;
            int rB = rA + 8;
            int tA = seq_start + ((rA < len) ? rA : (len - 1));
            int tB = seq_start + ((rB < len) ? rB : (len - 1));
            const float* qA = q + (size_t)tA * NH * HD + (size_t)h * HD;
            const float* qB = q + (size_t)tB * NH * HD + (size_t)h * HD;
#pragma unroll
            for (int ks = 0; ks < 8; ks++) {
                int c0 = ks * 16 + tg * 2;
                float2 a = *reinterpret_cast<const float2*>(qA + c0);
                float2 bb2 = *reinterpret_cast<const float2*>(qB + c0);
                float2 c = *reinterpret_cast<const float2*>(qA + c0 + 8);
                float2 d = *reinterpret_cast<const float2*>(qB + c0 + 8);
                qf[ks][0] = ph2(a.x * SCALE_LOG2E, a.y * SCALE_LOG2E);
                qf[ks][1] = ph2(bb2.x * SCALE_LOG2E, bb2.y * SCALE_LOG2E);
                qf[ks][2] = ph2(c.x * SCALE_LOG2E, c.y * SCALE_LOG2E);
                qf[ks][3] = ph2(d.x * SCALE_LOG2E, d.y * SCALE_LOG2E);
            }
        }

        const int nk     = (len < q0 + BM) ? len : (q0 + BM);
        const int ntiles = (nk + BN - 1) / BN;

        // next ticket; wait KV tile0
        if (t == 0) s_item = atomicAdd(&g_ctr, 1);
        cpa_wait0();
        __syncthreads();
        int next = s_item;

        float O[16][4];
#pragma unroll
        for (int nb = 0; nb < 16; nb++)
#pragma unroll
            for (int i = 0; i < 4; i++) O[nb][i] = 0.0f;
        float lc[4] = {0.0f, 0.0f, 0.0f, 0.0f};

        const int row0 = q0 + w * 16 + g;
        const int row1 = row0 + 8;
        const int wband_lo = q0 + w * 16;
        const int wband_hi = q0 + w * 16 + 15;

        for (int it = 0; it < ntiles; it++) {
            const int k0  = it * BN;
            const int cur = it & 1;

            if (it + 1 < ntiles) {
                issue_kv(sK + (cur ^ 1) * SKV_HALF, sV + (cur ^ 1) * SKV_HALF,
                         t, seq_start, seq_end, hk, k0 + BN);
                cpa_commit();
            }

            if (k0 <= wband_hi) {
                const half* kb = sK + cur * SKV_HALF;
                const half* vb = sV + cur * SKV_HALF;
                const bool do_mask = (k0 + BN - 1 > wband_lo);

                float S[8][4];
#pragma unroll
                for (int nb = 0; nb < 8; nb++)
#pragma unroll
                    for (int i = 0; i < 4; i++) S[nb][i] = 0.0f;

                // ---- QK chunk0 (cols 0..31) ----
#pragma unroll
                for (int ks = 0; ks < 8; ks++) {
#pragma unroll
                    for (int p = 0; p < 2; p++) {
                        uint32_t fk[4];
                        ldsm_x4(fk, sptr(kb + (p * 16 + krow) * SSTR + ks * 16 + kcol));
                        mma16816(S[2 * p],     qf[ks], fk[0], fk[1]);
                        mma16816(S[2 * p + 1], qf[ks], fk[2], fk[3]);
                    }
                }

                // ---- softmax chunk0 -> pa[0..1] ----
                uint32_t pa[4][4];
                if (do_mask) {
#pragma unroll
                    for (int nb = 0; nb < 4; nb++) {
                        int j0 = k0 + nb * 8 + 2 * tg;
                        int j1 = j0 + 1;
                        if (j0 > row0) S[nb][0] = -1e30f;
                        if (j1 > row0) S[nb][1] = -1e30f;
                        if (j0 > row1) S[nb][2] = -1e30f;
                        if (j1 > row1) S[nb][3] = -1e30f;
                    }
                }
#pragma unroll
                for (int nb = 0; nb < 4; nb++) {
                    float p0 = fexp2(S[nb][0] - FIXMAX);
                    float p1 = fexp2(S[nb][1] - FIXMAX);
                    float p2 = fexp2(S[nb][2] - FIXMAX);
                    float p3 = fexp2(S[nb][3] - FIXMAX);
                    int kb2 = nb >> 1;
                    int off = (nb & 1) * 2;
                    pa[kb2][off]     = ph2(p0, p1);
                    pa[kb2][off + 1] = ph2(p2, p3);
                }

                // ---- QK chunk1 (cols 32..63) ----
#pragma unroll
                for (int ks = 0; ks < 8; ks++) {
#pragma unroll
                    for (int p = 2; p < 4; p++) {
                        uint32_t fk[4];
                        ldsm_x4(fk, sptr(kb + (p * 16 + krow) * SSTR + ks * 16 + kcol));
                        mma16816(S[2 * p],     qf[ks], fk[0], fk[1]);
                        mma16816(S[2 * p + 1], qf[ks], fk[2], fk[3]);
                    }
                }

                // ---- l + PV chunk0 ----
                mma16816(lc, pa[0], ONESH2, ONESH2);
                mma16816(lc, pa[1], ONESH2, ONESH2);
#pragma unroll
                for (int kb2 = 0; kb2 < 2; kb2++) {
#pragma unroll
                    for (int p = 0; p < 8; p++) {
                        uint32_t fv[4];
                        ldsm_x4_t(fv, sptr(vb + (kb2 * 16 + vrow) * SSTR + p * 16 + vcol));
                        mma16816(O[2 * p],     pa[kb2], fv[0], fv[1]);
                        mma16816(O[2 * p + 1], pa[kb2], fv[2], fv[3]);
                    }
                }

                // ---- softmax chunk1 -> pa[2..3] ----
                if (do_mask) {
#pragma unroll
                    for (int nb = 4; nb < 8; nb++) {
                        int j0 = k0 + nb * 8 + 2 * tg;
                        int j1 = j0 + 1;
                        if (j0 > row0) S[nb][0] = -1e30f;
                        if (j1 > row0) S[nb][1] = -1e30f;
                        if (j0 > row1) S[nb][2] = -1e30f;
                        if (j1 > row1) S[nb][3] = -1e30f;
                    }
                }
#pragma unroll
                for (int nb = 4; nb < 8; nb++) {
                    float p0 = fexp2(S[nb][0] - FIXMAX);
                    float p1 = fexp2(S[nb][1] - FIXMAX);
                    float p2 = fexp2(S[nb][2] - FIXMAX);
                    float p3 = fexp2(S[nb][3] - FIXMAX);
                    int kb2 = nb >> 1;
                    int off = (nb & 1) * 2;
                    pa[kb2][off]     = ph2(p0, p1);
                    pa[kb2][off + 1] = ph2(p2, p3);
                }

                // ---- l + PV chunk1 ----
                mma16816(lc, pa[2], ONESH2, ONESH2);
                mma16816(lc, pa[3], ONESH2, ONESH2);
#pragma unroll
                for (int kb2 = 2; kb2 < 4; kb2++) {
#pragma unroll
                    for (int p = 0; p < 8; p++) {
                        uint32_t fv[4];
                        ldsm_x4_t(fv, sptr(vb + (kb2 * 16 + vrow) * SSTR + p * 16 + vcol));
                        mma16816(O[2 * p],     pa[kb2], fv[0], fv[1]);
                        mma16816(O[2 * p + 1], pa[kb2], fv[2], fv[3]);
                    }
                }
            }

            if (it + 1 < ntiles) {
                cpa_wait0();
                __syncthreads();
            }
        }

        // ---- epilogue ----
        float inv0 = 1.0f / lc[0];
        float inv1 = 1.0f / lc[2];
        if (row0 < len) {
            float* outr = out + (size_t)(seq_start + row0) * NH * HD + (size_t)h * HD;
#pragma unroll
            for (int nb = 0; nb < 16; nb++)
                *reinterpret_cast<float2*>(outr + nb * 8 + 2 * tg) =
                    make_float2(O[nb][0] * inv0, O[nb][1] * inv0);
        }
        if (row1 < len) {
            float* outr = out + (size_t)(seq_start + row1) * NH * HD + (size_t)h * HD;
#pragma unroll
            for (int nb = 0; nb < 16; nb++)
                *reinterpret_cast<float2*>(outr + nb * 8 + 2 * tg) =
                    make_float2(O[nb][2] * inv1, O[nb][3] * inv1);
        }
        __syncthreads();   // KV smem reused by next item
        item = next;
    }
}

// ---- preconvert K/V to fp16 (+ counter reset), 2-way ILP ----
__global__ void preconv_kv_kernel(const float* __restrict__ k,
                                  const float* __restrict__ v, int half_n8)
{
    int i = blockIdx.x * blockDim.x + threadIdx.x;
    if (i == 0) g_ctr = 0;
    if (i >= half_n8) return;
    size_t i0 = (size_t)i * 8;
    size_t i1 = (size_t)(i + half_n8) * 8;

    float4 a0 = *reinterpret_cast<const float4*>(k + i0);
    float4 b0 = *reinterpret_cast<const float4*>(k + i0 + 4);
    float4 c0 = *reinterpret_cast<const float4*>(v + i0);
    float4 d0 = *reinterpret_cast<const float4*>(v + i0 + 4);
    float4 a1 = *reinterpret_cast<const float4*>(k + i1);
    float4 b1 = *reinterpret_cast<const float4*>(k + i1 + 4);
    float4 c1 = *reinterpret_cast<const float4*>(v + i1);
    float4 d1 = *reinterpret_cast<const float4*>(v + i1 + 4);

    uint4 ko0, vo0, ko1, vo1;
    ko0.x = ph2(a0.x, a0.y); ko0.y = ph2(a0.z, a0.w);
    ko0.z = ph2(b0.x, b0.y); ko0.w = ph2(b0.z, b0.w);
    vo0.x = ph2(c0.x, c0.y); vo0.y = ph2(c0.z, c0.w);
    vo0.z = ph2(d0.x, d0.y); vo0.w = ph2(d0.z, d0.w);
    ko1.x = ph2(a1.x, a1.y); ko1.y = ph2(a1.z, a1.w);
    ko1.z = ph2(b1.x, b1.y); ko1.w = ph2(b1.z, b1.w);
    vo1.x = ph2(c1.x, c1.y); vo1.y = ph2(c1.z, c1.w);
    vo1.z = ph2(d1.x, d1.y); vo1.w = ph2(d1.z, d1.w);

    *reinterpret_cast<uint4*>(g_kh + i0) = ko0;
    *reinterpret_cast<uint4*>(g_vh + i0) = vo0;
    *reinterpret_cast<uint4*>(g_kh + i1) = ko1;
    *reinterpret_cast<uint4*>(g_vh + i1) = vo1;
}

__global__ void cache_copy_kernel(const float* __restrict__ kc_in,
                                  const float* __restrict__ vc_in,
                                  float* __restrict__ kc_out,
                                  float* __restrict__ vc_out,
                                  int n4)
{
    int i = blockIdx.x * blockDim.x + threadIdx.x;
    if (i < n4) {
        reinterpret_cast<float4*>(kc_out)[i] = reinterpret_cast<const float4*>(kc_in)[i];
        reinterpret_cast<float4*>(vc_out)[i] = reinterpret_cast<const float4*>(vc_in)[i];
    }
}

__global__ void kv_scatter_kernel(const float* __restrict__ k,
                                  const float* __restrict__ v,
                                  const int* __restrict__ slot_mapping,
                                  float* __restrict__ kc_out,
                                  float* __restrict__ vc_out,
                                  int T)
{
    int i = blockIdx.x * blockDim.x + threadIdx.x;
    int per_tok4 = NHK * HD / 4;
    int tok = i / per_tok4;
    int rem = i % per_tok4;
    if (tok >= T) return;
    int slot = slot_mapping[tok];
    if (slot < 0) return;
    reinterpret_cast<float4*>(kc_out)[(size_t)slot * per_tok4 + rem] =
        reinterpret_cast<const float4*>(k)[(size_t)tok * per_tok4 + rem];
    reinterpret_cast<float4*>(vc_out)[(size_t)slot * per_tok4 + rem] =
        reinterpret_cast<const float4*>(v)[(size_t)tok * per_tok4 + rem];
}

extern "C" void kernel_launch(void* const* d_in, const int* in_sizes, int n_in,
                              void* d_out, int out_size)
{
    const float* q  = (const float*)d_in[0];
    const float* k  = (const float*)d_in[1];
    const float* v  = (const float*)d_in[2];
    const float* kc = (const float*)d_in[3];
    const float* vc = (const float*)d_in[4];
    const int* cu   = (const int*)d_in[5];
    const int* slot = (const int*)d_in[6];

    const int T = in_sizes[0] / (NH * HD);

    float* out_attn = (float*)d_out;
    float* out_kc   = out_attn + (size_t)T * NH * HD;
    float* out_vc   = out_kc + (size_t)NSLOTS * NHK * HD;

    static cudaStream_t side = nullptr;
    static cudaEvent_t evf = nullptr, evj = nullptr;
    if (!side) {
        cudaStreamCreateWithFlags(&side, cudaStreamNonBlocking);
        cudaEventCreateWithFlags(&evf, cudaEventDisableTiming);
        cudaEventCreateWithFlags(&evj, cudaEventDisableTiming);
        cudaFuncSetAttribute(attn_kernel,
                             cudaFuncAttributeMaxDynamicSharedMemorySize,
                             SMEM_BYTES);
    }

    // main stream: preconv runs ALONE first (full DRAM bandwidth)
    {
        int half_n8 = T * NHK * HD / 16;
        preconv_kv_kernel<<<(half_n8 + 255) / 256, 256>>>(k, v, half_n8);
    }

    // fork AFTER preconv: cache maintenance overlaps attention
    cudaEventRecord(evf, 0);
    cudaStreamWaitEvent(side, evf, 0);
    {
        int n4 = NSLOTS * NHK * HD / 4;
        cache_copy_kernel<<<(n4 + 255) / 256, 256, 0, side>>>(kc, vc, out_kc, out_vc, n4);
        int total4 = T * NHK * HD / 4;
        kv_scatter_kernel<<<(total4 + 255) / 256, 256, 0, side>>>(k, v, slot, out_kc, out_vc, T);
    }
    cudaEventRecord(evj, side);

    // main stream: persistent attention (12 warps/SM)
    attn_kernel<<<NPERSIST, NTHREADS, SMEM_BYTES>>>(q, cu, out_attn);

    cudaStreamWaitEvent(0, evj, 0);
}